// round 2
// baseline (speedup 1.0000x reference)
#include <cuda_runtime.h>
#include <math.h>

// Problem constants (CTCLoss_70961449664599): T=2048, B=64, V=512, S=256
#define T_DIM 2048
#define B_DIM 64
#define V_DIM 512
#define S_DIM 256
#define L_DIM (2 * S_DIM + 1)   // 513 extended positions
#define GP    272               // padded gathered-row length (257 used, 16B-aligned rows)
#define NEG2  (-1.0e30f)
#define LOG2E_F 1.4426950408889634f
#define LN2_F   0.6931471805599453f

// Scratch (allocation-free rule: __device__ globals)
__device__ float g_G[(size_t)T_DIM * B_DIM * GP];   // ~142 MB: gathered log2-probs
__device__ float g_partial[B_DIM];

__device__ __forceinline__ float ex2f_(float x) {
    float y; asm("ex2.approx.f32 %0, %1;" : "=f"(y) : "f"(x)); return y;
}
__device__ __forceinline__ float lg2f_(float x) {
    float y; asm("lg2.approx.f32 %0, %1;" : "=f"(y) : "f"(x)); return y;
}

// ---------------------------------------------------------------------------
// Phase 1: per (t,b) row -> lse2 = log2(sum exp(x)); write gathered log2-probs
//   G[t][b][0] = blank symbol 0;  G[t][b][j] = targets[b][j-1], j = 1..256
// Grid: (B, T/8), block: 256 threads (8 warps, 1 warp per t-row)
// ---------------------------------------------------------------------------
__global__ __launch_bounds__(256) void ctc_phase1(
    const float* __restrict__ x, const int* __restrict__ targets)
{
    __shared__ float sh_row[8][V_DIM];
    __shared__ int   sh_tgt[S_DIM];

    const int b    = blockIdx.x;
    const int tid  = threadIdx.x;
    const int w    = tid >> 5;
    const int lane = tid & 31;

    sh_tgt[tid] = targets[b * S_DIM + tid];   // 256 threads cover 256 targets
    __syncthreads();

    const int t = blockIdx.y * 8 + w;
    const float4* row = (const float4*)(x + ((size_t)t * B_DIM + b) * V_DIM);

    float s = 0.0f;
    float4* shv = (float4*)sh_row[w];
#pragma unroll
    for (int k = 0; k < 4; k++) {
        float4 v = row[lane + 32 * k];
        shv[lane + 32 * k] = v;
        s += ex2f_(v.x * LOG2E_F) + ex2f_(v.y * LOG2E_F)
           + ex2f_(v.z * LOG2E_F) + ex2f_(v.w * LOG2E_F);
    }
#pragma unroll
    for (int o = 16; o; o >>= 1) s += __shfl_xor_sync(0xffffffffu, s, o);
    const float lse2 = lg2f_(s);   // warp is converged; shfl result uniform

    float* gout = g_G + ((size_t)t * B_DIM + b) * GP;
#pragma unroll
    for (int j = lane; j < 257; j += 32) {
        const int sym = (j == 0) ? 0 : sh_tgt[j - 1];
        gout[j] = sh_row[w][sym] * LOG2E_F - lse2;
    }
}

// ---------------------------------------------------------------------------
// Phase 2: alpha recursion. One block per batch element, 544 threads (17 warps),
// one position per thread, log2-domain, double-buffered alpha in SMEM,
// depth-8 register prefetch of the G column, one __syncthreads per time step.
// ---------------------------------------------------------------------------
#define NTH 544
#define PF  8
__global__ __launch_bounds__(NTH) void ctc_phase2(
    const int* __restrict__ targets,
    const int* __restrict__ in_len,
    const int* __restrict__ tgt_len)
{
    __shared__ float abuf[2][L_DIM + 2];   // [0],[1] are permanent NEG2 pads

    const int b   = blockIdx.x;
    const int tid = threadIdx.x;
    const int Lin = in_len[b];             // uniform across block
    const int Lt  = tgt_len[b];

    const int  l   = tid;
    const bool act = (l < L_DIM);
    const int  j   = (l & 1) ? ((l >> 1) + 1) : 0;   // symbol column in G

    bool allow2 = false;
    if (act && (l & 1)) {
        const int si   = (l - 1) >> 1;
        const int curt = targets[b * S_DIM + si];
        const int prev = (si > 0) ? targets[b * S_DIM + si - 1] : 0;
        allow2 = (curt != 0) && (curt != prev);
    }

    // init pads + alpha(t=0): only positions 0,1 live
    if (tid < 2) { abuf[0][tid] = NEG2; abuf[1][tid] = NEG2; }
    const size_t stride = (size_t)B_DIM * GP;
    const float* gcol = g_G + (size_t)b * GP + j;
    if (act) abuf[0][2 + l] = (l < 2) ? gcol[0] : NEG2;
    __syncthreads();

    int cur = 0;
    float pf[PF];
#pragma unroll
    for (int k = 0; k < PF; k++) {
        int tt = 1 + k; if (tt > T_DIM - 1) tt = T_DIM - 1;
        pf[k] = act ? __ldg(gcol + (size_t)tt * stride) : 0.0f;
    }

    for (int t0 = 1; t0 < Lin; t0 += PF) {
        float use[PF];
#pragma unroll
        for (int k = 0; k < PF; k++) use[k] = pf[k];
        // prefetch next chunk (clamped; values past Lin are discarded)
#pragma unroll
        for (int k = 0; k < PF; k++) {
            int tt = t0 + PF + k; if (tt > T_DIM - 1) tt = T_DIM - 1;
            pf[k] = act ? __ldg(gcol + (size_t)tt * stride) : 0.0f;
        }
#pragma unroll
        for (int k = 0; k < PF; k++) {
            if (t0 + k >= Lin) break;           // uniform across block
            if (act) {
                const float* A = abuf[cur];
                const float a0 = A[2 + l];
                const float a1 = A[1 + l];
                const float a2 = allow2 ? A[l] : NEG2;
                const float m  = fmaxf(a0, fmaxf(a1, a2));
                const float sm = ex2f_(a0 - m) + ex2f_(a1 - m) + ex2f_(a2 - m);
                abuf[cur ^ 1][2 + l] = m + lg2f_(sm) + use[k];
            }
            __syncthreads();
            cur ^= 1;
        }
    }

    if (tid == 0) {
        const float* A = abuf[cur];
        const int idx = 2 * Lt;
        const float aL = A[2 + idx];
        const float aP = A[1 + idx];
        const float m  = fmaxf(aL, aP);
        const float la2 = m + lg2f_(ex2f_(aL - m) + ex2f_(aP - m));
        float loss = -la2 * LN2_F;
        if (!isfinite(loss) || loss > 0.5e30f) loss = 0.0f;   // zero_infinity
        g_partial[b] = loss / (float)Lt;                      // per-sample mean part
    }
}

// ---------------------------------------------------------------------------
// Phase 3: mean over batch -> out[0]
// ---------------------------------------------------------------------------
__global__ void ctc_phase3(float* __restrict__ out)
{
    const int lane = threadIdx.x;
    float v = g_partial[lane] + g_partial[lane + 32];
#pragma unroll
    for (int o = 16; o; o >>= 1) v += __shfl_xor_sync(0xffffffffu, v, o);
    if (lane == 0) out[0] = v / (float)B_DIM;
}

// ---------------------------------------------------------------------------
extern "C" void kernel_launch(void* const* d_in, const int* in_sizes, int n_in,
                              void* d_out, int out_size)
{
    const float* x    = (const float*)d_in[0];   // (T, B, V) float32
    const int*   tgt  = (const int*)d_in[1];     // (B, S) int32
    const int*   ilen = (const int*)d_in[2];     // (B,) int32
    const int*   tlen = (const int*)d_in[3];     // (B,) int32
    float*       out  = (float*)d_out;

    dim3 g1(B_DIM, T_DIM / 8);
    ctc_phase1<<<g1, 256>>>(x, tgt);
    ctc_phase2<<<B_DIM, NTH>>>(tgt, ilen, tlen);
    ctc_phase3<<<1, 32>>>(out);
}